// round 2
// baseline (speedup 1.0000x reference)
#include <cuda_runtime.h>
#include <cuda_bf16.h>

// QuantumLinear: B=4096, IN_F=1024, NQ=4, L=2, C=256 circuits.
// Closed-form <Z_q> via Heisenberg propagation through RX layers + CNOT ring.
// alpha_q = x_q + w[c,0,q] (batch-dependent), beta_q = w[c,1,q] (per-circuit).

static constexpr int NCIRC = 256;

// Per-circuit coefficient table: 4 x float4 per circuit = 16 KB total.
// [0] = w0 angles (alpha offsets)
// [1] = a0..a3 for <Z0>
// [2] = (b0, b1, d0, d1) for <Z1>, <Z2>
// [3] = e0..e3 for <Z3>
__device__ float4 g_coef[NCIRC * 4];

__global__ void qprep_kernel(const float* __restrict__ w) {
    int c = threadIdx.x;                 // one thread per circuit
    const float* wc = w + c * 8;         // weights[c, 2, 4]
    float cb[4], sb[4];
#pragma unroll
    for (int q = 0; q < 4; q++) {
        __sincosf(wc[4 + q], &sb[q], &cb[q]);   // beta_q = w[c,1,q]
    }
    float c1c2 = cb[1] * cb[2];
    float s1s2 = sb[1] * sb[2];
    g_coef[c * 4 + 0] = make_float4(wc[0], wc[1], wc[2], wc[3]);
    // <Z0> coeffs: a0=c1c2c3, a1=c1c2s3, a2=s1s2c3, a3=s1s2s3
    g_coef[c * 4 + 1] = make_float4(c1c2 * cb[3], c1c2 * sb[3],
                                    s1s2 * cb[3], s1s2 * sb[3]);
    // <Z1>: b0=c0c1, b1=s0s1 ; <Z2>: d0=c0c1c2, d1=c0s1s2
    g_coef[c * 4 + 2] = make_float4(cb[0] * cb[1], sb[0] * sb[1],
                                    cb[0] * c1c2, cb[0] * s1s2);
    // <Z3>: e0=c0c1c2c3, e1=c0s1s2s3, e2=s0c1s2s3, e3=s0s1c2c3
    g_coef[c * 4 + 3] = make_float4(cb[0] * c1c2 * cb[3],
                                    cb[0] * s1s2 * sb[3],
                                    sb[0] * cb[1] * sb[2] * sb[3],
                                    sb[0] * sb[1] * cb[2] * cb[3]);
}

__global__ void __launch_bounds__(256) qmain_kernel(
    const float4* __restrict__ x, float4* __restrict__ out)
{
    int c = threadIdx.x;                              // circuit index 0..255
    int idx = blockIdx.x * 256 + c;                   // (b, c) flattened
    float4 xv = x[idx];                               // 4 input angles

    float4 k0 = g_coef[c * 4 + 0];
    float4 ka = g_coef[c * 4 + 1];
    float4 kb = g_coef[c * 4 + 2];
    float4 ke = g_coef[c * 4 + 3];

    float S0, C0, S1, C1, S2, C2, S3, C3;
    __sincosf(xv.x + k0.x, &S0, &C0);
    __sincosf(xv.y + k0.y, &S1, &C1);
    __sincosf(xv.z + k0.z, &S2, &C2);
    __sincosf(xv.w + k0.w, &S3, &C3);

    float C1C3 = C1 * C3;
    float S1S3 = S1 * S3;
    float C0C2 = C0 * C2;
    float S0S2 = S0 * S2;

    // <Z0> = C1C3*(a0*C0 + a3*S0) + S1S3*(a1*S0 + a2*C0)
    float z0 = fmaf(C1C3, fmaf(ka.x, C0, ka.w * S0),
                    S1S3 * fmaf(ka.y, S0, ka.z * C0));
    // <Z1> = C3*(b0*C0C2 + b1*S0S2)
    float z1 = C3 * fmaf(kb.x, C0C2, kb.y * S0S2);
    // <Z2> = d0*C1C3 + d1*S1S3
    float z2 = fmaf(kb.z, C1C3, kb.w * S1S3);
    // <Z3> = C2*(e0*C0 + e1*S0) + S2*(e2*C0 + e3*S0)
    float z3 = fmaf(C2, fmaf(ke.x, C0, ke.y * S0),
                    S2 * fmaf(ke.z, C0, ke.w * S0));

    out[idx] = make_float4(z0, z1, z2, z3);
}

extern "C" void kernel_launch(void* const* d_in, const int* in_sizes, int n_in,
                              void* d_out, int out_size) {
    const float* x = (const float*)d_in[0];       // (4096, 1024) f32
    const float* w = (const float*)d_in[1];       // (256, 2, 4)  f32
    float* out = (float*)d_out;                   // (4096, 1024) f32

    qprep_kernel<<<1, NCIRC>>>(w);
    qmain_kernel<<<4096, 256>>>((const float4*)x, (float4*)out);
}

// round 3
// speedup vs baseline: 1.9568x; 1.9568x over previous
#include <cuda_runtime.h>
#include <cuda_bf16.h>

// QuantumLinear: B=4096, IN_F=1024, NQ=4, L=2, C=256 circuits.
// Closed-form <Z_q> via Heisenberg propagation (exact):
//   alpha_q = x_q + w[c,0,q], beta_q = w[c,1,q]
//   <Z0> = C1C3*(a0*C0 + a3*S0) + S1S3*(a1*S0 + a2*C0)
//   <Z1> = C3*(c0c1*C0C2 + s0s1*S0S2)
//   <Z2> = c0c1c2*C1C3 + c0s1s2*S1S3
//   <Z3> = C2*(e0*C0 + e1*S0) + S2*(e2*C0 + e3*S0)
// Single fused kernel: each thread owns circuit c, computes its coefficient
// set in registers from w, and processes ROWS batch rows (amortizing the
// uncoalesced-ish w access and the beta sincos over ROWS rows).

static constexpr int NCIRC = 256;
static constexpr int ROWS  = 8;     // batch rows per thread

__global__ void __launch_bounds__(NCIRC) qfused_kernel(
    const float4* __restrict__ x,     // (B*256) float4
    const float4* __restrict__ w4,    // (256*2) float4  = weights (256,2,4)
    float4* __restrict__ out)         // (B*256) float4
{
    const int c = threadIdx.x;                 // circuit 0..255
    const int b0 = blockIdx.x * ROWS;          // first batch row

    // ---- per-circuit coefficients (registers) ----
    const float4 w0 = w4[c * 2 + 0];           // alpha offsets
    const float4 w1 = w4[c * 2 + 1];           // beta angles
    float cb0, sb0, cb1, sb1, cb2, sb2, cb3, sb3;
    __sincosf(w1.x, &sb0, &cb0);
    __sincosf(w1.y, &sb1, &cb1);
    __sincosf(w1.z, &sb2, &cb2);
    __sincosf(w1.w, &sb3, &cb3);

    const float c1c2 = cb1 * cb2;
    const float s1s2 = sb1 * sb2;
    // <Z0> coeffs
    const float a0 = c1c2 * cb3, a1 = c1c2 * sb3;
    const float a2 = s1s2 * cb3, a3 = s1s2 * sb3;
    // <Z1>/<Z2> coeffs
    const float p0 = cb0 * cb1,  p1 = sb0 * sb1;
    const float d0 = cb0 * c1c2, d1 = cb0 * s1s2;
    // <Z3> coeffs
    const float e0 = cb0 * c1c2 * cb3;
    const float e1 = cb0 * s1s2 * sb3;
    const float e2 = sb0 * cb1 * sb2 * sb3;
    const float e3 = sb0 * sb1 * cb2 * cb3;

    // ---- batch rows ----
#pragma unroll
    for (int r = 0; r < ROWS; r++) {
        const int idx = (b0 + r) * NCIRC + c;
        const float4 xv = x[idx];

        float S0, C0, S1, C1, S2, C2, S3, C3;
        __sincosf(xv.x + w0.x, &S0, &C0);
        __sincosf(xv.y + w0.y, &S1, &C1);
        __sincosf(xv.z + w0.z, &S2, &C2);
        __sincosf(xv.w + w0.w, &S3, &C3);

        const float C1C3 = C1 * C3;
        const float S1S3 = S1 * S3;
        const float C0C2 = C0 * C2;
        const float S0S2 = S0 * S2;

        float4 z;
        z.x = fmaf(C1C3, fmaf(a0, C0, a3 * S0), S1S3 * fmaf(a1, S0, a2 * C0));
        z.y = C3 * fmaf(p0, C0C2, p1 * S0S2);
        z.z = fmaf(d0, C1C3, d1 * S1S3);
        z.w = fmaf(C2, fmaf(e0, C0, e1 * S0), S2 * fmaf(e2, C0, e3 * S0));

        out[idx] = z;
    }
}

extern "C" void kernel_launch(void* const* d_in, const int* in_sizes, int n_in,
                              void* d_out, int out_size) {
    const float* x = (const float*)d_in[0];       // (4096, 1024) f32
    const float* w = (const float*)d_in[1];       // (256, 2, 4)  f32
    float* out = (float*)d_out;                   // (4096, 1024) f32

    const int B = 4096;
    qfused_kernel<<<B / ROWS, NCIRC>>>(
        (const float4*)x, (const float4*)w, (float4*)out);
}